// round 1
// baseline (speedup 1.0000x reference)
#include <cuda_runtime.h>
#include <math.h>

// ---------------------------------------------------------------------------
// SwitchHeadCore: B=2,S=2048,D=1024,H=8,E=4,K=2,DH=128
// Pipeline:
//   1) router_kernel : dense top-2 sigmoid gates for V (from k_src) and O (from q_src)
//   2) proj_kernel   : q = (q_src @ Wq^T)*s  -> [B,H,S,DH] ; same for k
//   3) vmix_kernel   : per head h, GEMM with expanded K (E*D) folding gates -> v [B,H,S,DH]
//   4) attn_kernel   : flash-style fp32 SDPA per (b,h) -> res [B,H,S,DH]
//   5) out_kernel    : GEMM with K=H*E*DH folding O gates -> out [B,S,D]
// ---------------------------------------------------------------------------

#define B_ 2
#define S_ 2048
#define D_ 1024
#define H_ 8
#define E_ 4
#define DH_ 128
#define TOK_ (B_ * S_)              // 4096
#define GE_ (H_ * E_)               // 32

__device__ float g_q[TOK_ * D_];     // [B,H,S,DH]
__device__ float g_k[TOK_ * D_];
__device__ float g_v[TOK_ * D_];
__device__ float g_res[TOK_ * D_];
__device__ float g_gv[TOK_ * GE_];   // dense V gates (0 if not top-2)
__device__ float g_go[TOK_ * GE_];   // dense O gates

// ---------------------------------------------------------------------------
// Router: one block per token. Computes sigmoid(x @ sel^T), top-2 of 4 per head,
// writes dense gates.
// ---------------------------------------------------------------------------
__global__ void router_kernel(const float* __restrict__ q_src,
                              const float* __restrict__ k_src,
                              const float* __restrict__ sel_v,
                              const float* __restrict__ sel_o) {
    int t = blockIdx.x;
    int tid = threadIdx.x;
    __shared__ float xs[D_];
    __shared__ float sg[GE_];

    for (int r = 0; r < 2; r++) {
        const float* src = (r == 0) ? k_src : q_src;
        const float* sel = (r == 0) ? sel_v : sel_o;
        float* gout      = (r == 0) ? g_gv  : g_go;

        for (int i = tid; i < D_ / 4; i += blockDim.x)
            ((float4*)xs)[i] = ((const float4*)(src + (size_t)t * D_))[i];
        __syncthreads();

        int g = tid >> 3;      // 0..31 output index
        int l8 = tid & 7;
        const float* w = sel + (size_t)g * D_;
        float sum = 0.f;
        for (int d = l8; d < D_; d += 8) sum += xs[d] * w[d];
        sum += __shfl_xor_sync(0xffffffffu, sum, 1);
        sum += __shfl_xor_sync(0xffffffffu, sum, 2);
        sum += __shfl_xor_sync(0xffffffffu, sum, 4);
        if (l8 == 0) sg[g] = 1.f / (1.f + __expf(-sum));
        __syncthreads();

        if (tid < H_) {
            int h = tid;
            float vals[4];
            #pragma unroll
            for (int e = 0; e < 4; e++) vals[e] = sg[h * 4 + e];
            int i1 = 0;
            #pragma unroll
            for (int e = 1; e < 4; e++) if (vals[e] > vals[i1]) i1 = e;
            int i2 = -1;
            #pragma unroll
            for (int e = 0; e < 4; e++) {
                if (e == i1) continue;
                if (i2 < 0 || vals[e] > vals[i2]) i2 = e;
            }
            #pragma unroll
            for (int e = 0; e < 4; e++) {
                float gv = (e == i1 || e == i2) ? vals[e] : 0.f;
                gout[(size_t)t * GE_ + h * 4 + e] = gv;
            }
        }
        __syncthreads();
    }
}

// ---------------------------------------------------------------------------
// Q/K projection: C[m,n] = scale * sum_k X[m,k]*W[n,k]; M=4096,N=1024,K=1024.
// Output written in [B,H,S,DH] layout.  128x128x8 tile, 8x8 micro (quadrant map).
// ---------------------------------------------------------------------------
__global__ __launch_bounds__(256) void proj_kernel(const float* __restrict__ X,
                                                   const float* __restrict__ W,
                                                   float* __restrict__ outp) {
    const float scale = 0.29730177875068026f; // 128^-0.25
    __shared__ __align__(16) float As[8][128];
    __shared__ __align__(16) float Bs[8][128];
    int tid = threadIdx.x;
    int tx = tid & 15, ty = tid >> 4;
    int m0 = blockIdx.y * 128, n0 = blockIdx.x * 128;

    float acc[8][8];
    #pragma unroll
    for (int i = 0; i < 8; i++)
        #pragma unroll
        for (int j = 0; j < 8; j++) acc[i][j] = 0.f;

    int lr = tid >> 1;
    int lk = (tid & 1) * 4;
    const float* Ap = X + (size_t)(m0 + lr) * D_ + lk;
    const float* Bp = W + (size_t)(n0 + lr) * D_ + lk;

    for (int kt = 0; kt < D_; kt += 8) {
        float4 a4 = *(const float4*)(Ap + kt);
        float4 b4 = *(const float4*)(Bp + kt);
        As[lk + 0][lr] = a4.x; As[lk + 1][lr] = a4.y;
        As[lk + 2][lr] = a4.z; As[lk + 3][lr] = a4.w;
        Bs[lk + 0][lr] = b4.x; Bs[lk + 1][lr] = b4.y;
        Bs[lk + 2][lr] = b4.z; Bs[lk + 3][lr] = b4.w;
        __syncthreads();
        #pragma unroll
        for (int kk = 0; kk < 8; kk++) {
            float a[8], bb[8];
            *(float4*)&a[0]  = *(const float4*)&As[kk][ty * 4];
            *(float4*)&a[4]  = *(const float4*)&As[kk][64 + ty * 4];
            *(float4*)&bb[0] = *(const float4*)&Bs[kk][tx * 4];
            *(float4*)&bb[4] = *(const float4*)&Bs[kk][64 + tx * 4];
            #pragma unroll
            for (int i = 0; i < 8; i++)
                #pragma unroll
                for (int j = 0; j < 8; j++) acc[i][j] += a[i] * bb[j];
        }
        __syncthreads();
    }

    #pragma unroll
    for (int iq = 0; iq < 2; iq++)
        #pragma unroll
        for (int i = 0; i < 4; i++) {
            int m = m0 + iq * 64 + ty * 4 + i;
            int b = m >> 11, s = m & (S_ - 1);
            #pragma unroll
            for (int jq = 0; jq < 2; jq++) {
                int n = n0 + jq * 64 + tx * 4;
                int h = n >> 7, dh = n & 127;
                float4 o;
                o.x = acc[iq * 4 + i][jq * 4 + 0] * scale;
                o.y = acc[iq * 4 + i][jq * 4 + 1] * scale;
                o.z = acc[iq * 4 + i][jq * 4 + 2] * scale;
                o.w = acc[iq * 4 + i][jq * 4 + 3] * scale;
                *(float4*)&outp[(((size_t)b * H_ + h) * S_ + s) * DH_ + dh] = o;
            }
        }
}

// ---------------------------------------------------------------------------
// V mix: per head h, v[t,:] = sum_e gate[t,h,e] * (v_src[t,:] @ Wv[h,e]).
// GEMM M=4096, N=128, K=E*D=4096 with gates folded into A loader.
// ---------------------------------------------------------------------------
__global__ __launch_bounds__(256) void vmix_kernel(const float* __restrict__ v_src,
                                                   const float* __restrict__ Wv) {
    int h = blockIdx.z;
    int m0 = blockIdx.y * 128;
    __shared__ __align__(16) float As[8][128];
    __shared__ __align__(16) float Bs[8][128];
    __shared__ float sG[128][4];
    int tid = threadIdx.x;
    int tx = tid & 15, ty = tid >> 4;

    for (int i = tid; i < 128 * 4; i += 256) {
        int r = i >> 2, e = i & 3;
        sG[r][e] = g_gv[(size_t)(m0 + r) * GE_ + h * 4 + e];
    }
    __syncthreads();

    float acc[8][8];
    #pragma unroll
    for (int i = 0; i < 8; i++)
        #pragma unroll
        for (int j = 0; j < 8; j++) acc[i][j] = 0.f;

    int lr = tid >> 1;
    int lk = (tid & 1) * 4;
    int brow = tid >> 5;
    int bn = (tid & 31) * 4;
    const float* Bbase = Wv + (size_t)h * E_ * D_ * DH_;   // [E*D][DH] contiguous

    for (int kt = 0; kt < E_ * D_; kt += 8) {
        int kk0 = kt + lk;
        int e = kk0 >> 10;
        int d0 = kk0 & 1023;
        float gg = sG[lr][e];
        float4 a4 = *(const float4*)(v_src + (size_t)(m0 + lr) * D_ + d0);
        As[lk + 0][lr] = a4.x * gg; As[lk + 1][lr] = a4.y * gg;
        As[lk + 2][lr] = a4.z * gg; As[lk + 3][lr] = a4.w * gg;
        *(float4*)&Bs[brow][bn] = *(const float4*)(Bbase + (size_t)(kt + brow) * DH_ + bn);
        __syncthreads();
        #pragma unroll
        for (int kk = 0; kk < 8; kk++) {
            float a[8], bb[8];
            *(float4*)&a[0]  = *(const float4*)&As[kk][ty * 4];
            *(float4*)&a[4]  = *(const float4*)&As[kk][64 + ty * 4];
            *(float4*)&bb[0] = *(const float4*)&Bs[kk][tx * 4];
            *(float4*)&bb[4] = *(const float4*)&Bs[kk][64 + tx * 4];
            #pragma unroll
            for (int i = 0; i < 8; i++)
                #pragma unroll
                for (int j = 0; j < 8; j++) acc[i][j] += a[i] * bb[j];
        }
        __syncthreads();
    }

    #pragma unroll
    for (int iq = 0; iq < 2; iq++)
        #pragma unroll
        for (int i = 0; i < 4; i++) {
            int m = m0 + iq * 64 + ty * 4 + i;
            int b = m >> 11, s = m & (S_ - 1);
            #pragma unroll
            for (int jq = 0; jq < 2; jq++) {
                int n = jq * 64 + tx * 4;  // dh
                float4 o;
                o.x = acc[iq * 4 + i][jq * 4 + 0];
                o.y = acc[iq * 4 + i][jq * 4 + 1];
                o.z = acc[iq * 4 + i][jq * 4 + 2];
                o.w = acc[iq * 4 + i][jq * 4 + 3];
                *(float4*)&g_v[(((size_t)b * H_ + h) * S_ + s) * DH_ + n] = o;
            }
        }
}

// ---------------------------------------------------------------------------
// Flash-style fp32 attention. Per (b,h): grid.y = b*H+h, grid.x = q tile (64 rows).
// Shared: Qs[64][132], KP (Kt [128][68] aliased with P [64][68]), Vs[64][132].
// Threads 256: tx=tid&15 (cols), ty=tid>>4 (q rows /4).
// ---------------------------------------------------------------------------
#define ATTN_SMEM ((64*132 + 128*68 + 64*132) * 4)

__global__ __launch_bounds__(256) void attn_kernel() {
    extern __shared__ __align__(16) float sm[];
    float* Qs = sm;                       // [64][132]
    float* KP = Qs + 64 * 132;            // Kt [d=128][kv=68] / P [64][68]
    float* Vs = KP + 128 * 68;            // [64][132]

    int bh = blockIdx.y;
    int q0 = blockIdx.x * 64;
    const float* Qg = g_q + (size_t)bh * S_ * DH_;
    const float* Kg = g_k + (size_t)bh * S_ * DH_;
    const float* Vg = g_v + (size_t)bh * S_ * DH_;

    int tid = threadIdx.x;
    int tx = tid & 15, ty = tid >> 4;

    for (int i = tid; i < 64 * 32; i += 256) {
        int r = i >> 5, c4 = (i & 31) * 4;
        *(float4*)&Qs[r * 132 + c4] = *(const float4*)(Qg + (size_t)(q0 + r) * DH_ + c4);
    }

    float m_i[4], l_i[4], acc[4][8];
    #pragma unroll
    for (int i = 0; i < 4; i++) {
        m_i[i] = -1e30f;
        l_i[i] = 0.f;
        #pragma unroll
        for (int c = 0; c < 8; c++) acc[i][c] = 0.f;
    }

    for (int j0 = 0; j0 < S_; j0 += 64) {
        __syncthreads();  // previous tile's P/V reads done; Q visible on first iter
        for (int i = tid; i < 64 * 32; i += 256) {
            int r = i >> 5, c4 = (i & 31) * 4;
            float4 kv = *(const float4*)(Kg + (size_t)(j0 + r) * DH_ + c4);
            KP[(c4 + 0) * 68 + r] = kv.x;
            KP[(c4 + 1) * 68 + r] = kv.y;
            KP[(c4 + 2) * 68 + r] = kv.z;
            KP[(c4 + 3) * 68 + r] = kv.w;
            *(float4*)&Vs[r * 132 + c4] = *(const float4*)(Vg + (size_t)(j0 + r) * DH_ + c4);
        }
        __syncthreads();

        float sf[4][4];
        #pragma unroll
        for (int i = 0; i < 4; i++)
            #pragma unroll
            for (int j = 0; j < 4; j++) sf[i][j] = 0.f;

        for (int d = 0; d < DH_; d++) {
            float4 b4 = *(const float4*)&KP[d * 68 + tx * 4];
            float a0 = Qs[(ty * 4 + 0) * 132 + d];
            float a1 = Qs[(ty * 4 + 1) * 132 + d];
            float a2 = Qs[(ty * 4 + 2) * 132 + d];
            float a3 = Qs[(ty * 4 + 3) * 132 + d];
            sf[0][0] += a0 * b4.x; sf[0][1] += a0 * b4.y; sf[0][2] += a0 * b4.z; sf[0][3] += a0 * b4.w;
            sf[1][0] += a1 * b4.x; sf[1][1] += a1 * b4.y; sf[1][2] += a1 * b4.z; sf[1][3] += a1 * b4.w;
            sf[2][0] += a2 * b4.x; sf[2][1] += a2 * b4.y; sf[2][2] += a2 * b4.z; sf[2][3] += a2 * b4.w;
            sf[3][0] += a3 * b4.x; sf[3][1] += a3 * b4.y; sf[3][2] += a3 * b4.z; sf[3][3] += a3 * b4.w;
        }

        #pragma unroll
        for (int i = 0; i < 4; i++) {
            float rmax = fmaxf(fmaxf(sf[i][0], sf[i][1]), fmaxf(sf[i][2], sf[i][3]));
            rmax = fmaxf(rmax, __shfl_xor_sync(0xffffffffu, rmax, 1));
            rmax = fmaxf(rmax, __shfl_xor_sync(0xffffffffu, rmax, 2));
            rmax = fmaxf(rmax, __shfl_xor_sync(0xffffffffu, rmax, 4));
            rmax = fmaxf(rmax, __shfl_xor_sync(0xffffffffu, rmax, 8));
            float mnew = fmaxf(m_i[i], rmax);
            float sc = __expf(m_i[i] - mnew);
            float rsum = 0.f;
            #pragma unroll
            for (int j = 0; j < 4; j++) {
                sf[i][j] = __expf(sf[i][j] - mnew);
                rsum += sf[i][j];
            }
            rsum += __shfl_xor_sync(0xffffffffu, rsum, 1);
            rsum += __shfl_xor_sync(0xffffffffu, rsum, 2);
            rsum += __shfl_xor_sync(0xffffffffu, rsum, 4);
            rsum += __shfl_xor_sync(0xffffffffu, rsum, 8);
            l_i[i] = l_i[i] * sc + rsum;
            m_i[i] = mnew;
            #pragma unroll
            for (int c = 0; c < 8; c++) acc[i][c] *= sc;
        }

        __syncthreads();  // all done reading Kt before P overwrites it
        #pragma unroll
        for (int i = 0; i < 4; i++)
            #pragma unroll
            for (int j = 0; j < 4; j++)
                KP[(ty * 4 + i) * 68 + tx * 4 + j] = sf[i][j];
        __syncthreads();

        for (int kk = 0; kk < 64; kk++) {
            float p0 = KP[(ty * 4 + 0) * 68 + kk];
            float p1 = KP[(ty * 4 + 1) * 68 + kk];
            float p2 = KP[(ty * 4 + 2) * 68 + kk];
            float p3 = KP[(ty * 4 + 3) * 68 + kk];
            float4 va = *(const float4*)&Vs[kk * 132 + tx * 4];
            float4 vb = *(const float4*)&Vs[kk * 132 + 64 + tx * 4];
            acc[0][0] += p0 * va.x; acc[0][1] += p0 * va.y; acc[0][2] += p0 * va.z; acc[0][3] += p0 * va.w;
            acc[0][4] += p0 * vb.x; acc[0][5] += p0 * vb.y; acc[0][6] += p0 * vb.z; acc[0][7] += p0 * vb.w;
            acc[1][0] += p1 * va.x; acc[1][1] += p1 * va.y; acc[1][2] += p1 * va.z; acc[1][3] += p1 * va.w;
            acc[1][4] += p1 * vb.x; acc[1][5] += p1 * vb.y; acc[1][6] += p1 * vb.z; acc[1][7] += p1 * vb.w;
            acc[2][0] += p2 * va.x; acc[2][1] += p2 * va.y; acc[2][2] += p2 * va.z; acc[2][3] += p2 * va.w;
            acc[2][4] += p2 * vb.x; acc[2][5] += p2 * vb.y; acc[2][6] += p2 * vb.z; acc[2][7] += p2 * vb.w;
            acc[3][0] += p3 * va.x; acc[3][1] += p3 * va.y; acc[3][2] += p3 * va.z; acc[3][3] += p3 * va.w;
            acc[3][4] += p3 * vb.x; acc[3][5] += p3 * vb.y; acc[3][6] += p3 * vb.z; acc[3][7] += p3 * vb.w;
        }
    }

    float* Og = g_res + (size_t)bh * S_ * DH_;
    #pragma unroll
    for (int i = 0; i < 4; i++) {
        float inv = 1.0f / l_i[i];
        int r = q0 + ty * 4 + i;
        float4 o;
        o.x = acc[i][0] * inv; o.y = acc[i][1] * inv; o.z = acc[i][2] * inv; o.w = acc[i][3] * inv;
        *(float4*)&Og[(size_t)r * DH_ + tx * 4] = o;
        o.x = acc[i][4] * inv; o.y = acc[i][5] * inv; o.z = acc[i][6] * inv; o.w = acc[i][7] * inv;
        *(float4*)&Og[(size_t)r * DH_ + 64 + tx * 4] = o;
    }
}

// ---------------------------------------------------------------------------
// Output: out[t,o] = sum_{h,e,dh} go[t,h,e]*res[t,h,dh]*Wo[h,e,dh,o].
// GEMM M=4096,N=1024,K=4096 with gates folded into A loader; B = Wo flat [4096][1024].
// ---------------------------------------------------------------------------
__global__ __launch_bounds__(256) void out_kernel(const float* __restrict__ Wo,
                                                  float* __restrict__ outp) {
    int m0 = blockIdx.y * 128, n0 = blockIdx.x * 128;
    __shared__ __align__(16) float As[8][128];
    __shared__ __align__(16) float Bs[8][128];
    __shared__ float sG[128][32];
    int tid = threadIdx.x;
    int tx = tid & 15, ty = tid >> 4;

    for (int i = tid; i < 128 * 32; i += 256) {
        int r = i >> 5, gi = i & 31;
        sG[r][gi] = g_go[(size_t)(m0 + r) * GE_ + gi];
    }
    __syncthreads();

    float acc[8][8];
    #pragma unroll
    for (int i = 0; i < 8; i++)
        #pragma unroll
        for (int j = 0; j < 8; j++) acc[i][j] = 0.f;

    int lr = tid >> 1;
    int lk = (tid & 1) * 4;
    int brow = tid >> 5;
    int bn = (tid & 31) * 4;
    int m = m0 + lr;
    int b = m >> 11, s = m & (S_ - 1);

    for (int kt = 0; kt < GE_ * DH_; kt += 8) {
        int kk0 = kt + lk;
        int gi = kk0 >> 7;          // h*E+e
        int h = kk0 >> 9;
        int dh0 = kk0 & 127;
        float gg = sG[lr][gi];
        float4 a4 = *(const float4*)(g_res + (((size_t)b * H_ + h) * S_ + s) * DH_ + dh0);
        As[lk + 0][lr] = a4.x * gg; As[lk + 1][lr] = a4.y * gg;
        As[lk + 2][lr] = a4.z * gg; As[lk + 3][lr] = a4.w * gg;
        *(float4*)&Bs[brow][bn] = *(const float4*)(Wo + (size_t)(kt + brow) * D_ + n0 + bn);
        __syncthreads();
        #pragma unroll
        for (int kk = 0; kk < 8; kk++) {
            float a[8], bb[8];
            *(float4*)&a[0]  = *(const float4*)&As[kk][ty * 4];
            *(float4*)&a[4]  = *(const float4*)&As[kk][64 + ty * 4];
            *(float4*)&bb[0] = *(const float4*)&Bs[kk][tx * 4];
            *(float4*)&bb[4] = *(const float4*)&Bs[kk][64 + tx * 4];
            #pragma unroll
            for (int i = 0; i < 8; i++)
                #pragma unroll
                for (int j = 0; j < 8; j++) acc[i][j] += a[i] * bb[j];
        }
        __syncthreads();
    }

    #pragma unroll
    for (int iq = 0; iq < 2; iq++)
        #pragma unroll
        for (int i = 0; i < 4; i++) {
            int mm = m0 + iq * 64 + ty * 4 + i;
            #pragma unroll
            for (int jq = 0; jq < 2; jq++) {
                int n = n0 + jq * 64 + tx * 4;
                float4 o;
                o.x = acc[iq * 4 + i][jq * 4 + 0];
                o.y = acc[iq * 4 + i][jq * 4 + 1];
                o.z = acc[iq * 4 + i][jq * 4 + 2];
                o.w = acc[iq * 4 + i][jq * 4 + 3];
                *(float4*)&outp[(size_t)mm * D_ + n] = o;
            }
        }
}

// ---------------------------------------------------------------------------
extern "C" void kernel_launch(void* const* d_in, const int* in_sizes, int n_in,
                              void* d_out, int out_size) {
    const float* q_src = (const float*)d_in[0];
    const float* k_src = (const float*)d_in[1];
    const float* v_src = (const float*)d_in[2];
    const float* Wq    = (const float*)d_in[3];
    const float* Wk    = (const float*)d_in[4];
    const float* Wv    = (const float*)d_in[5];
    const float* Wo    = (const float*)d_in[6];
    const float* sel_v = (const float*)d_in[7];
    const float* sel_o = (const float*)d_in[8];
    float* outp = (float*)d_out;

    cudaFuncSetAttribute(attn_kernel, cudaFuncAttributeMaxDynamicSharedMemorySize, ATTN_SMEM);

    router_kernel<<<TOK_, 256>>>(q_src, k_src, sel_v, sel_o);

    float* gq; cudaGetSymbolAddress((void**)&gq, g_q);
    float* gk; cudaGetSymbolAddress((void**)&gk, g_k);

    proj_kernel<<<dim3(D_ / 128, TOK_ / 128), 256>>>(q_src, Wq, gq);
    proj_kernel<<<dim3(D_ / 128, TOK_ / 128), 256>>>(k_src, Wk, gk);
    vmix_kernel<<<dim3(1, TOK_ / 128, H_), 256>>>(v_src, Wv);
    attn_kernel<<<dim3(S_ / 64, B_ * H_), 256, ATTN_SMEM>>>();
    out_kernel<<<dim3(D_ / 128, TOK_ / 128), 256>>>(Wo, outp);
}

// round 3
// speedup vs baseline: 1.4703x; 1.4703x over previous
#include <cuda_runtime.h>
#include <math.h>
#include <stdint.h>

// ---------------------------------------------------------------------------
// SwitchHeadCore: B=2,S=2048,D=1024,H=8,E=4,K=2,DH=128
// router -> transpose(Wv,Wo) -> tf32 mma.sync GEMMs (q/k proj, v-all, out)
// + gated reduce/expand + fp32 flash attention.
// (tcgen05 unavailable: harness targets sm_103 base, not sm_103a)
// ---------------------------------------------------------------------------

#define B_ 2
#define S_ 2048
#define D_ 1024
#define H_ 8
#define E_ 4
#define DH_ 128
#define TOK_ (B_ * S_)              // 4096
#define GE_ (H_ * E_)               // 32
#define KEXP_ 4096                  // H*E*DH

__device__ float g_q[TOK_ * D_];     // [B,H,S,DH]
__device__ float g_k[TOK_ * D_];
__device__ float g_v[TOK_ * D_];
__device__ float g_res[TOK_ * D_];
__device__ float g_gv[TOK_ * GE_];
__device__ float g_go[TOK_ * GE_];
__device__ float g_yall[(size_t)TOK_ * KEXP_];  // all-expert V outputs
__device__ float g_aexp[(size_t)TOK_ * KEXP_];  // gated expanded res
__device__ float g_wvT[(size_t)KEXP_ * D_];     // [(h,e,dh), d]
__device__ float g_woT[(size_t)D_ * KEXP_];     // [o, (h,e,dh)]

// ============================ mma helpers ==================================
__device__ __forceinline__ uint32_t f2tf32(float f) {
    uint32_t u;
    asm("cvt.rna.tf32.f32 %0, %1;" : "=r"(u) : "f"(f));
    return u;
}
__device__ __forceinline__ void mma_tf32(float* d, const uint32_t* a, const uint32_t* b) {
    asm volatile(
        "mma.sync.aligned.m16n8k8.row.col.f32.tf32.tf32.f32 "
        "{%0,%1,%2,%3}, {%4,%5,%6,%7}, {%8,%9}, {%0,%1,%2,%3};\n"
        : "+f"(d[0]), "+f"(d[1]), "+f"(d[2]), "+f"(d[3])
        : "r"(a[0]), "r"(a[1]), "r"(a[2]), "r"(a[3]), "r"(b[0]), "r"(b[1]));
}

// ============================ router =======================================
__global__ void router_kernel(const float* __restrict__ q_src,
                              const float* __restrict__ k_src,
                              const float* __restrict__ sel_v,
                              const float* __restrict__ sel_o) {
    int t = blockIdx.x;
    int tid = threadIdx.x;
    __shared__ float xs[D_];
    __shared__ float sg[GE_];

    for (int r = 0; r < 2; r++) {
        const float* src = (r == 0) ? k_src : q_src;
        const float* sel = (r == 0) ? sel_v : sel_o;
        float* gout      = (r == 0) ? g_gv  : g_go;

        for (int i = tid; i < D_ / 4; i += blockDim.x)
            ((float4*)xs)[i] = ((const float4*)(src + (size_t)t * D_))[i];
        __syncthreads();

        int g = tid >> 3;
        int l8 = tid & 7;
        const float* w = sel + (size_t)g * D_;
        float sum = 0.f;
        for (int d = l8; d < D_; d += 8) sum += xs[d] * w[d];
        sum += __shfl_xor_sync(0xffffffffu, sum, 1);
        sum += __shfl_xor_sync(0xffffffffu, sum, 2);
        sum += __shfl_xor_sync(0xffffffffu, sum, 4);
        if (l8 == 0) sg[g] = 1.f / (1.f + __expf(-sum));
        __syncthreads();

        if (tid < H_) {
            int h = tid;
            float vals[4];
            #pragma unroll
            for (int e = 0; e < 4; e++) vals[e] = sg[h * 4 + e];
            int i1 = 0;
            #pragma unroll
            for (int e = 1; e < 4; e++) if (vals[e] > vals[i1]) i1 = e;
            int i2 = -1;
            #pragma unroll
            for (int e = 0; e < 4; e++) {
                if (e == i1) continue;
                if (i2 < 0 || vals[e] > vals[i2]) i2 = e;
            }
            #pragma unroll
            for (int e = 0; e < 4; e++)
                gout[(size_t)t * GE_ + h * 4 + e] = (e == i1 || e == i2) ? vals[e] : 0.f;
        }
        __syncthreads();
    }
}

// ============================ transpose ====================================
__global__ void transpose_kernel(const float* __restrict__ src, float* __restrict__ dst,
                                 int R, int C) {
    __shared__ float tile[32][33];
    size_t zo = (size_t)blockIdx.z * R * C;
    src += zo; dst += zo;
    int r0 = blockIdx.y * 32, c0 = blockIdx.x * 32;
    int x = threadIdx.x, y = threadIdx.y;
    #pragma unroll
    for (int i = 0; i < 32; i += 8)
        tile[y + i][x] = src[(size_t)(r0 + y + i) * C + c0 + x];
    __syncthreads();
    #pragma unroll
    for (int i = 0; i < 32; i += 8)
        dst[(size_t)(c0 + y + i) * R + r0 + x] = tile[x][y + i];
}

// ============================ tf32 mma GEMM ================================
// C[M,N] = alpha * A[M,K] @ B[N,K]^T.  Tile 128x128xBK32, 8 warps (2m x 4n),
// warp tile 64x32 via m16n8k8.  SMEM rows padded to 36 floats (conflict-free
// fragment LDS).  MODE 0: row-major C[m*ldc+n].  MODE 1: q/k [B,H,S,DH].
#define PAD_ 36

template<int MODE>
__global__ __launch_bounds__(256) void gemm_tf32(const float* __restrict__ A,
                                                 const float* __restrict__ B,
                                                 float* __restrict__ C,
                                                 int Ktot, int ldc, float alpha) {
    __shared__ __align__(16) uint32_t As[128 * PAD_];
    __shared__ __align__(16) uint32_t Bs[128 * PAD_];

    int tid = threadIdx.x;
    int wid = tid >> 5;
    int lane = tid & 31;
    int m0 = blockIdx.y * 128, n0 = blockIdx.x * 128;
    int m0w = (wid >> 2) * 64, n0w = (wid & 3) * 32;

    // loader mapping: 2 threads/row, 4 float4 per thread
    int row = tid >> 1, half = tid & 1;
    const float* Ap = A + (size_t)(m0 + row) * Ktot + half * 16;
    const float* Bp = B + (size_t)(n0 + row) * Ktot + half * 16;
    uint32_t sts_off = (uint32_t)(row * PAD_ + half * 16);

    float acc[4][4][4];
    #pragma unroll
    for (int i = 0; i < 4; i++)
        #pragma unroll
        for (int j = 0; j < 4; j++)
            #pragma unroll
            for (int c = 0; c < 4; c++) acc[i][j][c] = 0.f;

    int KT = Ktot >> 5;
    float4 ra[4], rb[4];

    // prologue: load + stage tile 0
    #pragma unroll
    for (int j = 0; j < 4; j++) {
        ra[j] = *(const float4*)(Ap + j * 4);
        rb[j] = *(const float4*)(Bp + j * 4);
    }
    #pragma unroll
    for (int j = 0; j < 4; j++) {
        uint4 ua = make_uint4(f2tf32(ra[j].x), f2tf32(ra[j].y), f2tf32(ra[j].z), f2tf32(ra[j].w));
        uint4 ub = make_uint4(f2tf32(rb[j].x), f2tf32(rb[j].y), f2tf32(rb[j].z), f2tf32(rb[j].w));
        *(uint4*)&As[sts_off + j * 4] = ua;
        *(uint4*)&Bs[sts_off + j * 4] = ub;
    }
    __syncthreads();

    int r4 = lane >> 2, c4 = lane & 3;

    for (int kt = 0; kt < KT; kt++) {
        if (kt + 1 < KT) {
            const float* ap = Ap + (kt + 1) * 32;
            const float* bp = Bp + (kt + 1) * 32;
            #pragma unroll
            for (int j = 0; j < 4; j++) {
                ra[j] = *(const float4*)(ap + j * 4);
                rb[j] = *(const float4*)(bp + j * 4);
            }
        }

        #pragma unroll
        for (int ks = 0; ks < 4; ks++) {
            int kb = ks * 8;
            uint32_t a[4][4], b[4][2];
            #pragma unroll
            for (int mi = 0; mi < 4; mi++) {
                int rr = (m0w + mi * 16 + r4) * PAD_ + kb + c4;
                a[mi][0] = As[rr];
                a[mi][1] = As[rr + 8 * PAD_];
                a[mi][2] = As[rr + 4];
                a[mi][3] = As[rr + 8 * PAD_ + 4];
            }
            #pragma unroll
            for (int ni = 0; ni < 4; ni++) {
                int rr = (n0w + ni * 8 + r4) * PAD_ + kb + c4;
                b[ni][0] = Bs[rr];
                b[ni][1] = Bs[rr + 4];
            }
            #pragma unroll
            for (int mi = 0; mi < 4; mi++)
                #pragma unroll
                for (int ni = 0; ni < 4; ni++)
                    mma_tf32(acc[mi][ni], a[mi], b[ni]);
        }

        if (kt + 1 < KT) {
            __syncthreads();
            #pragma unroll
            for (int j = 0; j < 4; j++) {
                uint4 ua = make_uint4(f2tf32(ra[j].x), f2tf32(ra[j].y), f2tf32(ra[j].z), f2tf32(ra[j].w));
                uint4 ub = make_uint4(f2tf32(rb[j].x), f2tf32(rb[j].y), f2tf32(rb[j].z), f2tf32(rb[j].w));
                *(uint4*)&As[sts_off + j * 4] = ua;
                *(uint4*)&Bs[sts_off + j * 4] = ub;
            }
            __syncthreads();
        }
    }

    // epilogue
    #pragma unroll
    for (int mi = 0; mi < 4; mi++) {
        int rloc0 = m0w + mi * 16 + r4;
        #pragma unroll
        for (int half_m = 0; half_m < 2; half_m++) {
            int m = m0 + rloc0 + half_m * 8;
            float* base;
            if (MODE == 0) {
                base = C + (size_t)m * ldc + n0;
            } else {
                int bb = m >> 11, ss = m & (S_ - 1);
                int h = n0 >> 7;
                base = C + (((size_t)bb * H_ + h) * S_ + ss) * DH_;
            }
            #pragma unroll
            for (int ni = 0; ni < 4; ni++) {
                int c = n0w + ni * 8 + c4 * 2;
                float2 o;
                o.x = acc[mi][ni][half_m * 2 + 0] * alpha;
                o.y = acc[mi][ni][half_m * 2 + 1] * alpha;
                *(float2*)(base + c) = o;
            }
        }
    }
}

// ============================ gated reduce (V) =============================
__global__ __launch_bounds__(256) void vgate_kernel() {
    int idx = blockIdx.x * 256 + threadIdx.x;   // 4096*8*32
    int dh4 = idx & 31;
    int h = (idx >> 5) & 7;
    int t = idx >> 8;
    int b = t >> 11, s = t & (S_ - 1);
    const float* y = g_yall + (size_t)t * KEXP_ + h * 512 + dh4 * 4;
    const float* g = g_gv + (size_t)t * GE_ + h * 4;
    float4 acc = make_float4(0.f, 0.f, 0.f, 0.f);
    #pragma unroll
    for (int e = 0; e < 4; e++) {
        float ge = g[e];
        float4 ye = *(const float4*)(y + e * 128);
        acc.x += ge * ye.x; acc.y += ge * ye.y; acc.z += ge * ye.z; acc.w += ge * ye.w;
    }
    *(float4*)&g_v[(((size_t)b * H_ + h) * S_ + s) * DH_ + dh4 * 4] = acc;
}

// ============================ gated expand (O) =============================
__global__ __launch_bounds__(256) void expand_kernel() {
    int idx = blockIdx.x * 256 + threadIdx.x;   // 4096*32*32
    int dh4 = idx & 31;
    int he = (idx >> 5) & 31;
    int t = idx >> 10;
    int h = he >> 2;
    int b = t >> 11, s = t & (S_ - 1);
    float g = g_go[(size_t)t * GE_ + he];
    float4 r = *(const float4*)&g_res[(((size_t)b * H_ + h) * S_ + s) * DH_ + dh4 * 4];
    r.x *= g; r.y *= g; r.z *= g; r.w *= g;
    *(float4*)&g_aexp[(size_t)t * KEXP_ + he * 128 + dh4 * 4] = r;
}

// ============================ attention (fp32 flash) =======================
#define ATTN_SMEM ((64*132 + 128*68 + 64*132) * 4)

__global__ __launch_bounds__(256) void attn_kernel() {
    extern __shared__ __align__(16) float sm[];
    float* Qs = sm;
    float* KP = Qs + 64 * 132;
    float* Vs = KP + 128 * 68;

    int bh = blockIdx.y;
    int q0 = blockIdx.x * 64;
    const float* Qg = g_q + (size_t)bh * S_ * DH_;
    const float* Kg = g_k + (size_t)bh * S_ * DH_;
    const float* Vg = g_v + (size_t)bh * S_ * DH_;

    int tid = threadIdx.x;
    int tx = tid & 15, ty = tid >> 4;

    for (int i = tid; i < 64 * 32; i += 256) {
        int r = i >> 5, c4 = (i & 31) * 4;
        *(float4*)&Qs[r * 132 + c4] = *(const float4*)(Qg + (size_t)(q0 + r) * DH_ + c4);
    }

    float m_i[4], l_i[4], acc[4][8];
    #pragma unroll
    for (int i = 0; i < 4; i++) {
        m_i[i] = -1e30f; l_i[i] = 0.f;
        #pragma unroll
        for (int c = 0; c < 8; c++) acc[i][c] = 0.f;
    }

    for (int j0 = 0; j0 < S_; j0 += 64) {
        __syncthreads();
        for (int i = tid; i < 64 * 32; i += 256) {
            int r = i >> 5, c4 = (i & 31) * 4;
            float4 kv = *(const float4*)(Kg + (size_t)(j0 + r) * DH_ + c4);
            KP[(c4 + 0) * 68 + r] = kv.x;
            KP[(c4 + 1) * 68 + r] = kv.y;
            KP[(c4 + 2) * 68 + r] = kv.z;
            KP[(c4 + 3) * 68 + r] = kv.w;
            *(float4*)&Vs[r * 132 + c4] = *(const float4*)(Vg + (size_t)(j0 + r) * DH_ + c4);
        }
        __syncthreads();

        float sf[4][4];
        #pragma unroll
        for (int i = 0; i < 4; i++)
            #pragma unroll
            for (int j = 0; j < 4; j++) sf[i][j] = 0.f;

        for (int d = 0; d < DH_; d++) {
            float4 b4 = *(const float4*)&KP[d * 68 + tx * 4];
            float a0 = Qs[(ty * 4 + 0) * 132 + d];
            float a1 = Qs[(ty * 4 + 1) * 132 + d];
            float a2 = Qs[(ty * 4 + 2) * 132 + d];
            float a3 = Qs[(ty * 4 + 3) * 132 + d];
            sf[0][0] += a0 * b4.x; sf[0][1] += a0 * b4.y; sf[0][2] += a0 * b4.z; sf[0][3] += a0 * b4.w;
            sf[1][0] += a1 * b4.x; sf[1][1] += a1 * b4.y; sf[1][2] += a1 * b4.z; sf[1][3] += a1 * b4.w;
            sf[2][0] += a2 * b4.x; sf[2][1] += a2 * b4.y; sf[2][2] += a2 * b4.z; sf[2][3] += a2 * b4.w;
            sf[3][0] += a3 * b4.x; sf[3][1] += a3 * b4.y; sf[3][2] += a3 * b4.z; sf[3][3] += a3 * b4.w;
        }

        #pragma unroll
        for (int i = 0; i < 4; i++) {
            float rmax = fmaxf(fmaxf(sf[i][0], sf[i][1]), fmaxf(sf[i][2], sf[i][3]));
            rmax = fmaxf(rmax, __shfl_xor_sync(0xffffffffu, rmax, 1));
            rmax = fmaxf(rmax, __shfl_xor_sync(0xffffffffu, rmax, 2));
            rmax = fmaxf(rmax, __shfl_xor_sync(0xffffffffu, rmax, 4));
            rmax = fmaxf(rmax, __shfl_xor_sync(0xffffffffu, rmax, 8));
            float mnew = fmaxf(m_i[i], rmax);
            float sc = __expf(m_i[i] - mnew);
            float rsum = 0.f;
            #pragma unroll
            for (int j = 0; j < 4; j++) {
                sf[i][j] = __expf(sf[i][j] - mnew);
                rsum += sf[i][j];
            }
            rsum += __shfl_xor_sync(0xffffffffu, rsum, 1);
            rsum += __shfl_xor_sync(0xffffffffu, rsum, 2);
            rsum += __shfl_xor_sync(0xffffffffu, rsum, 4);
            rsum += __shfl_xor_sync(0xffffffffu, rsum, 8);
            l_i[i] = l_i[i] * sc + rsum;
            m_i[i] = mnew;
            #pragma unroll
            for (int c = 0; c < 8; c++) acc[i][c] *= sc;
        }

        __syncthreads();
        #pragma unroll
        for (int i = 0; i < 4; i++)
            #pragma unroll
            for (int j = 0; j < 4; j++)
                KP[(ty * 4 + i) * 68 + tx * 4 + j] = sf[i][j];
        __syncthreads();

        for (int kk = 0; kk < 64; kk++) {
            float p0 = KP[(ty * 4 + 0) * 68 + kk];
            float p1 = KP[(ty * 4 + 1) * 68 + kk];
            float p2 = KP[(ty * 4 + 2) * 68 + kk];
            float p3 = KP[(ty * 4 + 3) * 68 + kk];
            float4 va = *(const float4*)&Vs[kk * 132 + tx * 4];
            float4 vb = *(const float4*)&Vs[kk * 132 + 64 + tx * 4];
            acc[0][0] += p0 * va.x; acc[0][1] += p0 * va.y; acc[0][2] += p0 * va.z; acc[0][3] += p0 * va.w;
            acc[0][4] += p0 * vb.x; acc[0][5] += p0 * vb.y; acc[0][6] += p0 * vb.z; acc[0][7] += p0 * vb.w;
            acc[1][0] += p1 * va.x; acc[1][1] += p1 * va.y; acc[1][2] += p1 * va.z; acc[1][3] += p1 * va.w;
            acc[1][4] += p1 * vb.x; acc[1][5] += p1 * vb.y; acc[1][6] += p1 * vb.z; acc[1][7] += p1 * vb.w;
            acc[2][0] += p2 * va.x; acc[2][1] += p2 * va.y; acc[2][2] += p2 * va.z; acc[2][3] += p2 * va.w;
            acc[2][4] += p2 * vb.x; acc[2][5] += p2 * vb.y; acc[2][6] += p2 * vb.z; acc[2][7] += p2 * vb.w;
            acc[3][0] += p3 * va.x; acc[3][1] += p3 * va.y; acc[3][2] += p3 * va.z; acc[3][3] += p3 * va.w;
            acc[3][4] += p3 * vb.x; acc[3][5] += p3 * vb.y; acc[3][6] += p3 * vb.z; acc[3][7] += p3 * vb.w;
        }
    }

    float* Og = g_res + (size_t)bh * S_ * DH_;
    #pragma unroll
    for (int i = 0; i < 4; i++) {
        float inv = 1.0f / l_i[i];
        int r = q0 + ty * 4 + i;
        float4 o;
        o.x = acc[i][0] * inv; o.y = acc[i][1] * inv; o.z = acc[i][2] * inv; o.w = acc[i][3] * inv;
        *(float4*)&Og[(size_t)r * DH_ + tx * 4] = o;
        o.x = acc[i][4] * inv; o.y = acc[i][5] * inv; o.z = acc[i][6] * inv; o.w = acc[i][7] * inv;
        *(float4*)&Og[(size_t)r * DH_ + 64 + tx * 4] = o;
    }
}

// ---------------------------------------------------------------------------
extern "C" void kernel_launch(void* const* d_in, const int* in_sizes, int n_in,
                              void* d_out, int out_size) {
    const float* q_src = (const float*)d_in[0];
    const float* k_src = (const float*)d_in[1];
    const float* v_src = (const float*)d_in[2];
    const float* Wq    = (const float*)d_in[3];
    const float* Wk    = (const float*)d_in[4];
    const float* Wv    = (const float*)d_in[5];
    const float* Wo    = (const float*)d_in[6];
    const float* sel_v = (const float*)d_in[7];
    const float* sel_o = (const float*)d_in[8];
    float* outp = (float*)d_out;

    cudaFuncSetAttribute(attn_kernel, cudaFuncAttributeMaxDynamicSharedMemorySize, ATTN_SMEM);

    float *gq, *gk, *gyall, *gaexp, *gwvT, *gwoT;
    cudaGetSymbolAddress((void**)&gq, g_q);
    cudaGetSymbolAddress((void**)&gk, g_k);
    cudaGetSymbolAddress((void**)&gyall, g_yall);
    cudaGetSymbolAddress((void**)&gaexp, g_aexp);
    cudaGetSymbolAddress((void**)&gwvT, g_wvT);
    cudaGetSymbolAddress((void**)&gwoT, g_woT);

    const float scale = 0.29730177875068026f;  // 128^-0.25

    router_kernel<<<TOK_, 256>>>(q_src, k_src, sel_v, sel_o);

    // Wv [H,E,D,DH] -> WvT [(h,e,dh), d]
    transpose_kernel<<<dim3(DH_ / 32, D_ / 32, GE_), dim3(32, 8)>>>(Wv, gwvT, D_, DH_);
    // Wo flat [(h,e,dh), o] -> WoT [o, (h,e,dh)]
    transpose_kernel<<<dim3(D_ / 32, KEXP_ / 32, 1), dim3(32, 8)>>>(Wo, gwoT, KEXP_, D_);

    // q/k projections: M=4096, N=1024, K=1024
    gemm_tf32<1><<<dim3(D_ / 128, TOK_ / 128), 256>>>(q_src, Wq, gq, D_, 0, scale);
    gemm_tf32<1><<<dim3(D_ / 128, TOK_ / 128), 256>>>(k_src, Wk, gk, D_, 0, scale);

    // all-expert V: M=4096, N=4096, K=1024
    gemm_tf32<0><<<dim3(KEXP_ / 128, TOK_ / 128), 256>>>(v_src, gwvT, gyall, D_, KEXP_, 1.0f);
    vgate_kernel<<<TOK_ * H_ * 32 / 256, 256>>>();

    attn_kernel<<<dim3(S_ / 64, B_ * H_), 256, ATTN_SMEM>>>();

    expand_kernel<<<TOK_ * GE_ * 32 / 256, 256>>>();
    // out: M=4096, N=1024, K=4096
    gemm_tf32<0><<<dim3(D_ / 128, TOK_ / 128), 256>>>(gaexp, gwoT, outp, KEXP_, D_, 1.0f);
}

// round 4
// speedup vs baseline: 2.3146x; 1.5742x over previous
#include <cuda_runtime.h>
#include <math.h>
#include <stdint.h>

// ---------------------------------------------------------------------------
// SwitchHeadCore: B=2,S=2048,D=1024,H=8,E=4,K=2,DH=128
// router -> transpose(Wv,Wo) -> tf32 mma.sync GEMMs (q/k proj, v-all, out w/
// folded O-gates) + gated V reduce + tf32 mma.sync flash attention.
// ---------------------------------------------------------------------------

#define B_ 2
#define S_ 2048
#define D_ 1024
#define H_ 8
#define E_ 4
#define DH_ 128
#define TOK_ (B_ * S_)              // 4096
#define GE_ (H_ * E_)               // 32
#define KEXP_ 4096                  // H*E*DH

__device__ float g_q[TOK_ * D_];     // [B,H,S,DH]
__device__ float g_k[TOK_ * D_];
__device__ float g_v[TOK_ * D_];
__device__ float g_res[TOK_ * D_];
__device__ float g_gv[TOK_ * GE_];
__device__ float g_go[TOK_ * GE_];
__device__ float g_yall[(size_t)TOK_ * KEXP_];  // all-expert V outputs
__device__ float g_wvT[(size_t)KEXP_ * D_];     // [(h,e,dh), d]
__device__ float g_woT[(size_t)D_ * KEXP_];     // [o, (h,e,dh)]

// ============================ mma helpers ==================================
__device__ __forceinline__ uint32_t f2tf32(float f) {
    uint32_t u;
    asm("cvt.rna.tf32.f32 %0, %1;" : "=r"(u) : "f"(f));
    return u;
}
__device__ __forceinline__ void mma_tf32(float* d, const uint32_t* a, const uint32_t* b) {
    asm volatile(
        "mma.sync.aligned.m16n8k8.row.col.f32.tf32.tf32.f32 "
        "{%0,%1,%2,%3}, {%4,%5,%6,%7}, {%8,%9}, {%0,%1,%2,%3};\n"
        : "+f"(d[0]), "+f"(d[1]), "+f"(d[2]), "+f"(d[3])
        : "r"(a[0]), "r"(a[1]), "r"(a[2]), "r"(a[3]), "r"(b[0]), "r"(b[1]));
}

// ============================ router =======================================
__global__ void router_kernel(const float* __restrict__ q_src,
                              const float* __restrict__ k_src,
                              const float* __restrict__ sel_v,
                              const float* __restrict__ sel_o) {
    int t = blockIdx.x;
    int tid = threadIdx.x;
    __shared__ float xs[D_];
    __shared__ float sg[GE_];

    for (int r = 0; r < 2; r++) {
        const float* src = (r == 0) ? k_src : q_src;
        const float* sel = (r == 0) ? sel_v : sel_o;
        float* gout      = (r == 0) ? g_gv  : g_go;

        for (int i = tid; i < D_ / 4; i += blockDim.x)
            ((float4*)xs)[i] = ((const float4*)(src + (size_t)t * D_))[i];
        __syncthreads();

        int g = tid >> 3;
        int l8 = tid & 7;
        const float* w = sel + (size_t)g * D_;
        float sum = 0.f;
        for (int d = l8; d < D_; d += 8) sum += xs[d] * w[d];
        sum += __shfl_xor_sync(0xffffffffu, sum, 1);
        sum += __shfl_xor_sync(0xffffffffu, sum, 2);
        sum += __shfl_xor_sync(0xffffffffu, sum, 4);
        if (l8 == 0) sg[g] = 1.f / (1.f + __expf(-sum));
        __syncthreads();

        if (tid < H_) {
            int h = tid;
            float vals[4];
            #pragma unroll
            for (int e = 0; e < 4; e++) vals[e] = sg[h * 4 + e];
            int i1 = 0;
            #pragma unroll
            for (int e = 1; e < 4; e++) if (vals[e] > vals[i1]) i1 = e;
            int i2 = -1;
            #pragma unroll
            for (int e = 0; e < 4; e++) {
                if (e == i1) continue;
                if (i2 < 0 || vals[e] > vals[i2]) i2 = e;
            }
            #pragma unroll
            for (int e = 0; e < 4; e++)
                gout[(size_t)t * GE_ + h * 4 + e] = (e == i1 || e == i2) ? vals[e] : 0.f;
        }
        __syncthreads();
    }
}

// ============================ transpose ====================================
__global__ void transpose_kernel(const float* __restrict__ src, float* __restrict__ dst,
                                 int R, int C) {
    __shared__ float tile[32][33];
    size_t zo = (size_t)blockIdx.z * R * C;
    src += zo; dst += zo;
    int r0 = blockIdx.y * 32, c0 = blockIdx.x * 32;
    int x = threadIdx.x, y = threadIdx.y;
    #pragma unroll
    for (int i = 0; i < 32; i += 8)
        tile[y + i][x] = src[(size_t)(r0 + y + i) * C + c0 + x];
    __syncthreads();
    #pragma unroll
    for (int i = 0; i < 32; i += 8)
        dst[(size_t)(c0 + y + i) * R + r0 + x] = tile[x][y + i];
}

// ============================ tf32 mma GEMM ================================
// C[M,N] = alpha * A[M,K] @ B[N,K]^T.  Tile 128x128xBK32, 8 warps (2m x 4n),
// warp tile 64x32 via m16n8k8.  PAD 36 rows (conflict-free fragment LDS).
// MODE 0: row-major C.  MODE 1: C in q/k layout [B,H,S,DH].
// MODE 2: A = g_go-gated expansion of g_res (A ptr = g_res), C row-major.
#define PAD_ 36

template<int MODE>
__global__ __launch_bounds__(256) void gemm_tf32(const float* __restrict__ A,
                                                 const float* __restrict__ B,
                                                 float* __restrict__ C,
                                                 int Ktot, int ldc, float alpha) {
    __shared__ __align__(16) uint32_t As[128 * PAD_];
    __shared__ __align__(16) uint32_t Bs[128 * PAD_];

    int tid = threadIdx.x;
    int wid = tid >> 5;
    int lane = tid & 31;
    int m0 = blockIdx.y * 128, n0 = blockIdx.x * 128;
    int m0w = (wid >> 2) * 64, n0w = (wid & 3) * 32;

    int row = tid >> 1, half = tid & 1;
    const float* Ap = A + (size_t)(m0 + row) * Ktot + half * 16;
    const float* Bp = B + (size_t)(n0 + row) * Ktot + half * 16;
    uint32_t sts_off = (uint32_t)(row * PAD_ + half * 16);

    // MODE 2 addressing
    int t2 = m0 + row;
    int bb2 = t2 >> 11, ss2 = t2 & (S_ - 1);
    const float* Rbase = A + (((size_t)bb2 * H_) * S_ + ss2) * DH_;  // + h*S*DH + dh
    const float* Gp = g_go + (size_t)t2 * GE_;

    float acc[4][4][4];
    #pragma unroll
    for (int i = 0; i < 4; i++)
        #pragma unroll
        for (int j = 0; j < 4; j++)
            #pragma unroll
            for (int c = 0; c < 4; c++) acc[i][j][c] = 0.f;

    int KT = Ktot >> 5;
    float4 ra[4], rb[4];

    auto loadA = [&](int kt) {
        if (MODE == 2) {
            #pragma unroll
            for (int j = 0; j < 4; j++) {
                int k = kt * 32 + half * 16 + j * 4;
                int he = k >> 7;
                int dh = k & 127;
                float4 v = *(const float4*)(Rbase + (size_t)(he >> 2) * S_ * DH_ + dh);
                float g = Gp[he];
                v.x *= g; v.y *= g; v.z *= g; v.w *= g;
                ra[j] = v;
            }
        } else {
            #pragma unroll
            for (int j = 0; j < 4; j++)
                ra[j] = *(const float4*)(Ap + kt * 32 + j * 4);
        }
        #pragma unroll
        for (int j = 0; j < 4; j++)
            rb[j] = *(const float4*)(Bp + kt * 32 + j * 4);
    };
    auto stage = [&]() {
        #pragma unroll
        for (int j = 0; j < 4; j++) {
            uint4 ua = make_uint4(f2tf32(ra[j].x), f2tf32(ra[j].y), f2tf32(ra[j].z), f2tf32(ra[j].w));
            uint4 ub = make_uint4(f2tf32(rb[j].x), f2tf32(rb[j].y), f2tf32(rb[j].z), f2tf32(rb[j].w));
            *(uint4*)&As[sts_off + j * 4] = ua;
            *(uint4*)&Bs[sts_off + j * 4] = ub;
        }
    };

    loadA(0);
    stage();
    __syncthreads();

    int r4 = lane >> 2, c4 = lane & 3;

    for (int kt = 0; kt < KT; kt++) {
        if (kt + 1 < KT) loadA(kt + 1);

        #pragma unroll
        for (int ks = 0; ks < 4; ks++) {
            int kb = ks * 8;
            uint32_t a[4][4], b[4][2];
            #pragma unroll
            for (int mi = 0; mi < 4; mi++) {
                int rr = (m0w + mi * 16 + r4) * PAD_ + kb + c4;
                a[mi][0] = As[rr];
                a[mi][1] = As[rr + 8 * PAD_];
                a[mi][2] = As[rr + 4];
                a[mi][3] = As[rr + 8 * PAD_ + 4];
            }
            #pragma unroll
            for (int ni = 0; ni < 4; ni++) {
                int rr = (n0w + ni * 8 + r4) * PAD_ + kb + c4;
                b[ni][0] = Bs[rr];
                b[ni][1] = Bs[rr + 4];
            }
            #pragma unroll
            for (int mi = 0; mi < 4; mi++)
                #pragma unroll
                for (int ni = 0; ni < 4; ni++)
                    mma_tf32(acc[mi][ni], a[mi], b[ni]);
        }

        if (kt + 1 < KT) {
            __syncthreads();
            stage();
            __syncthreads();
        }
    }

    #pragma unroll
    for (int mi = 0; mi < 4; mi++) {
        int rloc0 = m0w + mi * 16 + r4;
        #pragma unroll
        for (int half_m = 0; half_m < 2; half_m++) {
            int m = m0 + rloc0 + half_m * 8;
            float* base;
            if (MODE == 1) {
                int bb = m >> 11, ss = m & (S_ - 1);
                int h = n0 >> 7;
                base = C + (((size_t)bb * H_ + h) * S_ + ss) * DH_;
            } else {
                base = C + (size_t)m * ldc + n0;
            }
            #pragma unroll
            for (int ni = 0; ni < 4; ni++) {
                int c = n0w + ni * 8 + c4 * 2;
                float2 o;
                o.x = acc[mi][ni][half_m * 2 + 0] * alpha;
                o.y = acc[mi][ni][half_m * 2 + 1] * alpha;
                *(float2*)(base + c) = o;
            }
        }
    }
}

// ============================ gated reduce (V) =============================
__global__ __launch_bounds__(256) void vgate_kernel() {
    int idx = blockIdx.x * 256 + threadIdx.x;   // 4096*8*32
    int dh4 = idx & 31;
    int h = (idx >> 5) & 7;
    int t = idx >> 8;
    int b = t >> 11, s = t & (S_ - 1);
    const float* y = g_yall + (size_t)t * KEXP_ + h * 512 + dh4 * 4;
    const float* g = g_gv + (size_t)t * GE_ + h * 4;
    float4 acc = make_float4(0.f, 0.f, 0.f, 0.f);
    #pragma unroll
    for (int e = 0; e < 4; e++) {
        float ge = g[e];
        float4 ye = *(const float4*)(y + e * 128);
        acc.x += ge * ye.x; acc.y += ge * ye.y; acc.z += ge * ye.z; acc.w += ge * ye.w;
    }
    *(float4*)&g_v[(((size_t)b * H_ + h) * S_ + s) * DH_ + dh4 * 4] = acc;
}

// ============================ tf32 flash attention =========================
// q tile 128 (8 warps x 16 rows), kv tile 64.  All SMEM tiles tf32.
// Qs[128][132], Ks[64][132], Vt[128][68] (dh-major), Ps[128][68].
// Pads 132/68 == 4 (mod 32) -> conflict-free fragment LDS.
#define QP_ 132
#define VP_ 68
#define ATTN_SMEM ((128 * QP_ + 64 * QP_ + 128 * VP_ + 128 * VP_) * 4)

__global__ __launch_bounds__(256) void attn_tc_kernel() {
    extern __shared__ __align__(16) uint32_t asm_[];
    uint32_t* Qs = asm_;
    uint32_t* Ks = Qs + 128 * QP_;
    uint32_t* Vt = Ks + 64 * QP_;
    uint32_t* Ps = Vt + 128 * VP_;

    int bh = blockIdx.y;
    int q0 = blockIdx.x * 128;
    const float* Qg = g_q + (size_t)bh * S_ * DH_;
    const float* Kg = g_k + (size_t)bh * S_ * DH_;
    const float* Vg = g_v + (size_t)bh * S_ * DH_;

    int tid = threadIdx.x;
    int wid = tid >> 5;
    int lane = tid & 31;
    int r4 = lane >> 2, c4 = lane & 3;
    int m0w = wid * 16;

    // load Q (tf32)
    for (int i = tid; i < 128 * 32; i += 256) {
        int r = i >> 5, c = (i & 31) * 4;
        float4 v = *(const float4*)(Qg + (size_t)(q0 + r) * DH_ + c);
        uint4 u = make_uint4(f2tf32(v.x), f2tf32(v.y), f2tf32(v.z), f2tf32(v.w));
        *(uint4*)&Qs[r * QP_ + c] = u;
    }

    float o[16][4];
    #pragma unroll
    for (int ni = 0; ni < 16; ni++)
        #pragma unroll
        for (int c = 0; c < 4; c++) o[ni][c] = 0.f;
    float mA = -1e30f, mB = -1e30f, lA = 0.f, lB = 0.f;

    for (int j0 = 0; j0 < S_; j0 += 64) {
        __syncthreads();   // prev PV done reading Ks/Vt (and Q visible, iter 0)
        for (int i = tid; i < 64 * 32; i += 256) {
            int r = i >> 5, c = (i & 31) * 4;
            float4 kv = *(const float4*)(Kg + (size_t)(j0 + r) * DH_ + c);
            uint4 u = make_uint4(f2tf32(kv.x), f2tf32(kv.y), f2tf32(kv.z), f2tf32(kv.w));
            *(uint4*)&Ks[r * QP_ + c] = u;
        }
        for (int i = tid; i < 64 * 32; i += 256) {
            int r = i & 63, c = (i >> 6) * 4;   // lanes span rows -> conflict-free STS
            float4 vv = *(const float4*)(Vg + (size_t)(j0 + r) * DH_ + c);
            Vt[(c + 0) * VP_ + r] = f2tf32(vv.x);
            Vt[(c + 1) * VP_ + r] = f2tf32(vv.y);
            Vt[(c + 2) * VP_ + r] = f2tf32(vv.z);
            Vt[(c + 3) * VP_ + r] = f2tf32(vv.w);
        }
        __syncthreads();

        // S = Q K^T  (warp rows m0w..+15, all 64 kv cols)
        float sf[8][4];
        #pragma unroll
        for (int ni = 0; ni < 8; ni++)
            #pragma unroll
            for (int c = 0; c < 4; c++) sf[ni][c] = 0.f;

        #pragma unroll
        for (int ks = 0; ks < 16; ks++) {
            int kb = ks * 8;
            uint32_t a[4];
            int ar = (m0w + r4) * QP_ + kb + c4;
            a[0] = Qs[ar];
            a[1] = Qs[ar + 8 * QP_];
            a[2] = Qs[ar + 4];
            a[3] = Qs[ar + 8 * QP_ + 4];
            #pragma unroll
            for (int ni = 0; ni < 8; ni++) {
                uint32_t b[2];
                int br = (ni * 8 + r4) * QP_ + kb + c4;
                b[0] = Ks[br];
                b[1] = Ks[br + 4];
                mma_tf32(sf[ni], a, b);
            }
        }

        // online softmax (rows r4 and r4+8 of warp tile)
        float mxA = -1e30f, mxB = -1e30f;
        #pragma unroll
        for (int ni = 0; ni < 8; ni++) {
            mxA = fmaxf(mxA, fmaxf(sf[ni][0], sf[ni][1]));
            mxB = fmaxf(mxB, fmaxf(sf[ni][2], sf[ni][3]));
        }
        mxA = fmaxf(mxA, __shfl_xor_sync(0xffffffffu, mxA, 1));
        mxA = fmaxf(mxA, __shfl_xor_sync(0xffffffffu, mxA, 2));
        mxB = fmaxf(mxB, __shfl_xor_sync(0xffffffffu, mxB, 1));
        mxB = fmaxf(mxB, __shfl_xor_sync(0xffffffffu, mxB, 2));
        float mnA = fmaxf(mA, mxA), mnB = fmaxf(mB, mxB);
        float scA = __expf(mA - mnA), scB = __expf(mB - mnB);
        float sA = 0.f, sB = 0.f;
        int prA = (m0w + r4) * VP_;
        int prB = prA + 8 * VP_;
        #pragma unroll
        for (int ni = 0; ni < 8; ni++) {
            float e0 = __expf(sf[ni][0] - mnA);
            float e1 = __expf(sf[ni][1] - mnA);
            float e2 = __expf(sf[ni][2] - mnB);
            float e3 = __expf(sf[ni][3] - mnB);
            sA += e0 + e1; sB += e2 + e3;
            int cc = ni * 8 + c4 * 2;
            Ps[prA + cc] = f2tf32(e0); Ps[prA + cc + 1] = f2tf32(e1);
            Ps[prB + cc] = f2tf32(e2); Ps[prB + cc + 1] = f2tf32(e3);
        }
        sA += __shfl_xor_sync(0xffffffffu, sA, 1);
        sA += __shfl_xor_sync(0xffffffffu, sA, 2);
        sB += __shfl_xor_sync(0xffffffffu, sB, 1);
        sB += __shfl_xor_sync(0xffffffffu, sB, 2);
        lA = lA * scA + sA; lB = lB * scB + sB;
        mA = mnA; mB = mnB;
        #pragma unroll
        for (int ni = 0; ni < 16; ni++) {
            o[ni][0] *= scA; o[ni][1] *= scA;
            o[ni][2] *= scB; o[ni][3] *= scB;
        }
        __syncwarp();   // Ps rows are warp-private; make stores visible in-warp

        // O += P V   (A rows = warp's q rows, K = 64 kv, N = 128 dh)
        #pragma unroll
        for (int ks = 0; ks < 8; ks++) {
            int kb = ks * 8;
            uint32_t a[4];
            int ar = (m0w + r4) * VP_ + kb + c4;
            a[0] = Ps[ar];
            a[1] = Ps[ar + 8 * VP_];
            a[2] = Ps[ar + 4];
            a[3] = Ps[ar + 8 * VP_ + 4];
            #pragma unroll
            for (int ni = 0; ni < 16; ni++) {
                uint32_t b[2];
                int br = (ni * 8 + r4) * VP_ + kb + c4;
                b[0] = Vt[br];
                b[1] = Vt[br + 4];
                mma_tf32(o[ni], a, b);
            }
        }
    }

    float invA = 1.f / lA, invB = 1.f / lB;
    int rA = q0 + m0w + r4;
    float* OgA = g_res + (size_t)bh * S_ * DH_ + (size_t)rA * DH_;
    float* OgB = OgA + 8 * DH_;
    #pragma unroll
    for (int ni = 0; ni < 16; ni++) {
        int cc = ni * 8 + c4 * 2;
        float2 oa, ob;
        oa.x = o[ni][0] * invA; oa.y = o[ni][1] * invA;
        ob.x = o[ni][2] * invB; ob.y = o[ni][3] * invB;
        *(float2*)(OgA + cc) = oa;
        *(float2*)(OgB + cc) = ob;
    }
}

// ---------------------------------------------------------------------------
extern "C" void kernel_launch(void* const* d_in, const int* in_sizes, int n_in,
                              void* d_out, int out_size) {
    const float* q_src = (const float*)d_in[0];
    const float* k_src = (const float*)d_in[1];
    const float* v_src = (const float*)d_in[2];
    const float* Wq    = (const float*)d_in[3];
    const float* Wk    = (const float*)d_in[4];
    const float* Wv    = (const float*)d_in[5];
    const float* Wo    = (const float*)d_in[6];
    const float* sel_v = (const float*)d_in[7];
    const float* sel_o = (const float*)d_in[8];
    float* outp = (float*)d_out;

    cudaFuncSetAttribute(attn_tc_kernel, cudaFuncAttributeMaxDynamicSharedMemorySize, ATTN_SMEM);

    float *gq, *gk, *gyall, *gwvT, *gwoT, *gres;
    cudaGetSymbolAddress((void**)&gq, g_q);
    cudaGetSymbolAddress((void**)&gk, g_k);
    cudaGetSymbolAddress((void**)&gyall, g_yall);
    cudaGetSymbolAddress((void**)&gwvT, g_wvT);
    cudaGetSymbolAddress((void**)&gwoT, g_woT);
    cudaGetSymbolAddress((void**)&gres, g_res);

    const float scale = 0.29730177875068026f;  // 128^-0.25

    router_kernel<<<TOK_, 256>>>(q_src, k_src, sel_v, sel_o);

    // Wv [H,E,D,DH] -> WvT [(h,e,dh), d]
    transpose_kernel<<<dim3(DH_ / 32, D_ / 32, GE_), dim3(32, 8)>>>(Wv, gwvT, D_, DH_);
    // Wo flat [(h,e,dh), o] -> WoT [o, (h,e,dh)]
    transpose_kernel<<<dim3(D_ / 32, KEXP_ / 32, 1), dim3(32, 8)>>>(Wo, gwoT, KEXP_, D_);

    // q/k projections: M=4096, N=1024, K=1024
    gemm_tf32<1><<<dim3(D_ / 128, TOK_ / 128), 256>>>(q_src, Wq, gq, D_, 0, scale);
    gemm_tf32<1><<<dim3(D_ / 128, TOK_ / 128), 256>>>(k_src, Wk, gk, D_, 0, scale);

    // all-expert V: M=4096, N=4096, K=1024
    gemm_tf32<0><<<dim3(KEXP_ / 128, TOK_ / 128), 256>>>(v_src, gwvT, gyall, D_, KEXP_, 1.0f);
    vgate_kernel<<<TOK_ * H_ * 32 / 256, 256>>>();

    attn_tc_kernel<<<dim3(S_ / 128, B_ * H_), 256, ATTN_SMEM>>>();

    // out: M=4096, N=1024, K=4096, A = gated g_res expansion (MODE 2)
    gemm_tf32<2><<<dim3(D_ / 128, TOK_ / 128), 256>>>(gres, gwoT, outp, KEXP_, D_, 1.0f);
}

// round 5
// speedup vs baseline: 2.3607x; 1.0199x over previous
#include <cuda_runtime.h>
#include <math.h>
#include <stdint.h>

// ---------------------------------------------------------------------------
// SwitchHeadCore: B=2,S=2048,D=1024,H=8,E=4,K=2,DH=128
// router -> transpose(Wv,Wo) -> double-buffered tf32 mma.sync GEMMs
// (merged q/k proj, per-head gated V GEMM, gated out GEMM) + tf32 flash attn.
// ---------------------------------------------------------------------------

#define B_ 2
#define S_ 2048
#define D_ 1024
#define H_ 8
#define E_ 4
#define DH_ 128
#define TOK_ (B_ * S_)              // 4096
#define GE_ (H_ * E_)               // 32
#define KEXP_ 4096                  // H*E*DH

__device__ float g_q[TOK_ * D_];     // [B,H,S,DH]
__device__ float g_k[TOK_ * D_];
__device__ float g_v[TOK_ * D_];
__device__ float g_res[TOK_ * D_];
__device__ float g_gv[TOK_ * GE_];
__device__ float g_go[TOK_ * GE_];
__device__ float g_wvT[(size_t)KEXP_ * D_];     // [(h,e,dh), d]
__device__ float g_woT[(size_t)D_ * KEXP_];     // [o, (h,e,dh)]

// ============================ mma helpers ==================================
__device__ __forceinline__ uint32_t f2tf32(float f) {
    uint32_t u;
    asm("cvt.rna.tf32.f32 %0, %1;" : "=r"(u) : "f"(f));
    return u;
}
__device__ __forceinline__ void mma_tf32(float* d, const uint32_t* a, const uint32_t* b) {
    asm volatile(
        "mma.sync.aligned.m16n8k8.row.col.f32.tf32.tf32.f32 "
        "{%0,%1,%2,%3}, {%4,%5,%6,%7}, {%8,%9}, {%0,%1,%2,%3};\n"
        : "+f"(d[0]), "+f"(d[1]), "+f"(d[2]), "+f"(d[3])
        : "r"(a[0]), "r"(a[1]), "r"(a[2]), "r"(a[3]), "r"(b[0]), "r"(b[1]));
}

// ============================ router =======================================
__global__ void router_kernel(const float* __restrict__ q_src,
                              const float* __restrict__ k_src,
                              const float* __restrict__ sel_v,
                              const float* __restrict__ sel_o) {
    int t = blockIdx.x;
    int tid = threadIdx.x;
    __shared__ float xs[D_];
    __shared__ float sg[GE_];

    for (int r = 0; r < 2; r++) {
        const float* src = (r == 0) ? k_src : q_src;
        const float* sel = (r == 0) ? sel_v : sel_o;
        float* gout      = (r == 0) ? g_gv  : g_go;

        for (int i = tid; i < D_ / 4; i += blockDim.x)
            ((float4*)xs)[i] = ((const float4*)(src + (size_t)t * D_))[i];
        __syncthreads();

        int g = tid >> 3;
        int l8 = tid & 7;
        const float* w = sel + (size_t)g * D_;
        float sum = 0.f;
        for (int d = l8; d < D_; d += 8) sum += xs[d] * w[d];
        sum += __shfl_xor_sync(0xffffffffu, sum, 1);
        sum += __shfl_xor_sync(0xffffffffu, sum, 2);
        sum += __shfl_xor_sync(0xffffffffu, sum, 4);
        if (l8 == 0) sg[g] = 1.f / (1.f + __expf(-sum));
        __syncthreads();

        if (tid < H_) {
            int h = tid;
            float vals[4];
            #pragma unroll
            for (int e = 0; e < 4; e++) vals[e] = sg[h * 4 + e];
            int i1 = 0;
            #pragma unroll
            for (int e = 1; e < 4; e++) if (vals[e] > vals[i1]) i1 = e;
            int i2 = -1;
            #pragma unroll
            for (int e = 0; e < 4; e++) {
                if (e == i1) continue;
                if (i2 < 0 || vals[e] > vals[i2]) i2 = e;
            }
            #pragma unroll
            for (int e = 0; e < 4; e++)
                gout[(size_t)t * GE_ + h * 4 + e] = (e == i1 || e == i2) ? vals[e] : 0.f;
        }
        __syncthreads();
    }
}

// ============================ transpose ====================================
__global__ void transpose_kernel(const float* __restrict__ src, float* __restrict__ dst,
                                 int R, int C) {
    __shared__ float tile[32][33];
    size_t zo = (size_t)blockIdx.z * R * C;
    src += zo; dst += zo;
    int r0 = blockIdx.y * 32, c0 = blockIdx.x * 32;
    int x = threadIdx.x, y = threadIdx.y;
    #pragma unroll
    for (int i = 0; i < 32; i += 8)
        tile[y + i][x] = src[(size_t)(r0 + y + i) * C + c0 + x];
    __syncthreads();
    #pragma unroll
    for (int i = 0; i < 32; i += 8)
        dst[(size_t)(c0 + y + i) * R + r0 + x] = tile[x][y + i];
}

// ============================ tf32 mma GEMM (double buffered) ==============
// C[M,N] = alpha * A @ B^T.  Tile 128x128xBK32, 8 warps (2m x 4n), warp 64x32.
// PAD 36 (conflict-free fragment LDS).  Dynamic SMEM: 2 buffers.
// MODE 1: merged q/k proj; blockIdx.z selects (A,B,C)=(q_src,Wq,g_q)/(k_src,Wk,g_k);
//         C layout [B,H,S,DH].
// MODE 2: A = g_go-gated expansion of g_res (A ptr = g_res), C row-major.
// MODE 3: per-head gated V: z=h, A[t, e*D+d] = gv[t,h,e]*v_src[t,d],
//         B[dh, e*D+d] = g_wvT[(h*4+e)*128+dh, d], C = g_v [B,H,S,DH].
#define PAD_ 36
#define GBUF_ (2 * 128 * PAD_)
#define GSMEM_BYTES (2 * GBUF_ * 4)

template<int MODE>
__global__ __launch_bounds__(256) void gemm_tf32(const float* __restrict__ A,
                                                 const float* __restrict__ B,
                                                 float* __restrict__ C,
                                                 int Ktot, int ldc, float alpha,
                                                 const float* __restrict__ A2,
                                                 const float* __restrict__ B2,
                                                 float* __restrict__ C2) {
    extern __shared__ __align__(16) uint32_t dsm[];

    int tid = threadIdx.x;
    int wid = tid >> 5;
    int lane = tid & 31;
    int m0 = blockIdx.y * 128, n0 = blockIdx.x * 128;
    int hz = blockIdx.z;
    int m0w = (wid >> 2) * 64, n0w = (wid & 3) * 32;

    if (MODE == 1 && hz == 1) { A = A2; B = B2; C = C2; }

    int row = tid >> 1, half = tid & 1;
    const float* Ap = A + (size_t)(m0 + row) * Ktot + half * 16;
    const float* Bp = B + (size_t)(n0 + row) * Ktot + half * 16;
    uint32_t sts_off = (uint32_t)(row * PAD_ + half * 16);

    // MODE 2 addressing
    int t2 = m0 + row;
    int bb2 = t2 >> 11, ss2 = t2 & (S_ - 1);
    const float* Rbase = A + (((size_t)bb2 * H_) * S_ + ss2) * DH_;
    const float* Gp2 = g_go + (size_t)t2 * GE_;
    // MODE 3 addressing
    const float* A3 = A + (size_t)t2 * D_ + half * 16;         // v_src row
    const float* Gp3 = g_gv + (size_t)t2 * GE_ + hz * 4;

    float acc[4][4][4];
    #pragma unroll
    for (int i = 0; i < 4; i++)
        #pragma unroll
        for (int j = 0; j < 4; j++)
            #pragma unroll
            for (int c = 0; c < 4; c++) acc[i][j][c] = 0.f;

    int KT = Ktot >> 5;
    float4 ra[4], rb[4];

    auto loadAB = [&](int kt) {
        if (MODE == 2) {
            #pragma unroll
            for (int j = 0; j < 4; j++) {
                int k = kt * 32 + half * 16 + j * 4;
                int he = k >> 7;
                int dh = k & 127;
                float4 v = *(const float4*)(Rbase + (size_t)(he >> 2) * S_ * DH_ + dh);
                float g = Gp2[he];
                v.x *= g; v.y *= g; v.z *= g; v.w *= g;
                ra[j] = v;
            }
            #pragma unroll
            for (int j = 0; j < 4; j++)
                rb[j] = *(const float4*)(Bp + kt * 32 + j * 4);
        } else if (MODE == 3) {
            int e = (kt * 32) >> 10;
            int d0 = (kt * 32) & 1023;
            float g = Gp3[e];
            #pragma unroll
            for (int j = 0; j < 4; j++) {
                float4 v = *(const float4*)(A3 + d0 + j * 4);
                v.x *= g; v.y *= g; v.z *= g; v.w *= g;
                ra[j] = v;
            }
            const float* bp = B + ((size_t)((hz * 4 + e) * 128 + row)) * D_ + d0 + half * 16;
            #pragma unroll
            for (int j = 0; j < 4; j++)
                rb[j] = *(const float4*)(bp + j * 4);
        } else {
            #pragma unroll
            for (int j = 0; j < 4; j++) {
                ra[j] = *(const float4*)(Ap + kt * 32 + j * 4);
                rb[j] = *(const float4*)(Bp + kt * 32 + j * 4);
            }
        }
    };
    auto stage = [&](int s) {
        uint32_t* As = dsm + s * GBUF_;
        uint32_t* Bs = As + 128 * PAD_;
        #pragma unroll
        for (int j = 0; j < 4; j++) {
            uint4 ua = make_uint4(f2tf32(ra[j].x), f2tf32(ra[j].y), f2tf32(ra[j].z), f2tf32(ra[j].w));
            uint4 ub = make_uint4(f2tf32(rb[j].x), f2tf32(rb[j].y), f2tf32(rb[j].z), f2tf32(rb[j].w));
            *(uint4*)&As[sts_off + j * 4] = ua;
            *(uint4*)&Bs[sts_off + j * 4] = ub;
        }
    };

    loadAB(0);
    stage(0);
    __syncthreads();

    int r4 = lane >> 2, c4 = lane & 3;

    for (int kt = 0; kt < KT; kt++) {
        if (kt + 1 < KT) loadAB(kt + 1);

        uint32_t* As = dsm + (kt & 1) * GBUF_;
        uint32_t* Bs = As + 128 * PAD_;
        #pragma unroll
        for (int ks = 0; ks < 4; ks++) {
            int kb = ks * 8;
            uint32_t a[4][4], b[4][2];
            #pragma unroll
            for (int mi = 0; mi < 4; mi++) {
                int rr = (m0w + mi * 16 + r4) * PAD_ + kb + c4;
                a[mi][0] = As[rr];
                a[mi][1] = As[rr + 8 * PAD_];
                a[mi][2] = As[rr + 4];
                a[mi][3] = As[rr + 8 * PAD_ + 4];
            }
            #pragma unroll
            for (int ni = 0; ni < 4; ni++) {
                int rr = (n0w + ni * 8 + r4) * PAD_ + kb + c4;
                b[ni][0] = Bs[rr];
                b[ni][1] = Bs[rr + 4];
            }
            #pragma unroll
            for (int mi = 0; mi < 4; mi++)
                #pragma unroll
                for (int ni = 0; ni < 4; ni++)
                    mma_tf32(acc[mi][ni], a[mi], b[ni]);
        }

        if (kt + 1 < KT) {
            stage((kt + 1) & 1);
            __syncthreads();
        }
    }

    #pragma unroll
    for (int mi = 0; mi < 4; mi++) {
        int rloc0 = m0w + mi * 16 + r4;
        #pragma unroll
        for (int half_m = 0; half_m < 2; half_m++) {
            int m = m0 + rloc0 + half_m * 8;
            float* base;
            if (MODE == 1 || MODE == 3) {
                int bb = m >> 11, ss = m & (S_ - 1);
                int h = (MODE == 3) ? hz : (n0 >> 7);
                base = C + (((size_t)bb * H_ + h) * S_ + ss) * DH_ + ((MODE == 3) ? 0 : 0);
            } else {
                base = C + (size_t)m * ldc + n0;
            }
            #pragma unroll
            for (int ni = 0; ni < 4; ni++) {
                int c = n0w + ni * 8 + c4 * 2;
                float2 o;
                o.x = acc[mi][ni][half_m * 2 + 0] * alpha;
                o.y = acc[mi][ni][half_m * 2 + 1] * alpha;
                *(float2*)(base + c) = o;
            }
        }
    }
}

// ============================ tf32 flash attention =========================
// q tile 128 (8 warps x 16 rows), kv tile 64, K/V register prefetch.
// Qs[128][132], Ks[64][132], Vt[128][68], Ps[128][68].
#define QP_ 132
#define VP_ 68
#define ATTN_SMEM ((128 * QP_ + 64 * QP_ + 128 * VP_ + 128 * VP_) * 4)

__global__ __launch_bounds__(256) void attn_tc_kernel() {
    extern __shared__ __align__(16) uint32_t asm_[];
    uint32_t* Qs = asm_;
    uint32_t* Ks = Qs + 128 * QP_;
    uint32_t* Vt = Ks + 64 * QP_;
    uint32_t* Ps = Vt + 128 * VP_;

    int bh = blockIdx.y;
    int q0 = blockIdx.x * 128;
    const float* Qg = g_q + (size_t)bh * S_ * DH_;
    const float* Kg = g_k + (size_t)bh * S_ * DH_;
    const float* Vg = g_v + (size_t)bh * S_ * DH_;

    int tid = threadIdx.x;
    int wid = tid >> 5;
    int lane = tid & 31;
    int r4 = lane >> 2, c4 = lane & 3;
    int m0w = wid * 16;

    // load Q (tf32)
    for (int i = tid; i < 128 * 32; i += 256) {
        int r = i >> 5, c = (i & 31) * 4;
        float4 v = *(const float4*)(Qg + (size_t)(q0 + r) * DH_ + c);
        uint4 u = make_uint4(f2tf32(v.x), f2tf32(v.y), f2tf32(v.z), f2tf32(v.w));
        *(uint4*)&Qs[r * QP_ + c] = u;
    }

    float4 kreg[8], vreg[8];
    auto loadK = [&](int j0) {
        #pragma unroll
        for (int j = 0; j < 8; j++) {
            int i = tid + 256 * j;
            int r = i >> 5, c = (i & 31) * 4;
            kreg[j] = *(const float4*)(Kg + (size_t)(j0 + r) * DH_ + c);
        }
    };
    auto loadV = [&](int j0) {
        #pragma unroll
        for (int j = 0; j < 8; j++) {
            int i = tid + 256 * j;
            int r = i & 63, c = (i >> 6) * 4;
            vreg[j] = *(const float4*)(Vg + (size_t)(j0 + r) * DH_ + c);
        }
    };

    loadK(0);
    loadV(0);

    float o[16][4];
    #pragma unroll
    for (int ni = 0; ni < 16; ni++)
        #pragma unroll
        for (int c = 0; c < 4; c++) o[ni][c] = 0.f;
    float mA = -1e30f, mB = -1e30f, lA = 0.f, lB = 0.f;

    for (int j0 = 0; j0 < S_; j0 += 64) {
        __syncthreads();   // prev tile's SMEM reads done (and Q visible, iter 0)
        #pragma unroll
        for (int j = 0; j < 8; j++) {
            int i = tid + 256 * j;
            int r = i >> 5, c = (i & 31) * 4;
            uint4 u = make_uint4(f2tf32(kreg[j].x), f2tf32(kreg[j].y),
                                 f2tf32(kreg[j].z), f2tf32(kreg[j].w));
            *(uint4*)&Ks[r * QP_ + c] = u;
        }
        #pragma unroll
        for (int j = 0; j < 8; j++) {
            int i = tid + 256 * j;
            int r = i & 63, c = (i >> 6) * 4;
            Vt[(c + 0) * VP_ + r] = f2tf32(vreg[j].x);
            Vt[(c + 1) * VP_ + r] = f2tf32(vreg[j].y);
            Vt[(c + 2) * VP_ + r] = f2tf32(vreg[j].z);
            Vt[(c + 3) * VP_ + r] = f2tf32(vreg[j].w);
        }
        __syncthreads();

        bool more = (j0 + 64) < S_;
        if (more) loadK(j0 + 64);   // overlap with S GEMM

        // S = Q K^T
        float sf[8][4];
        #pragma unroll
        for (int ni = 0; ni < 8; ni++)
            #pragma unroll
            for (int c = 0; c < 4; c++) sf[ni][c] = 0.f;

        #pragma unroll
        for (int ks = 0; ks < 16; ks++) {
            int kb = ks * 8;
            uint32_t a[4];
            int ar = (m0w + r4) * QP_ + kb + c4;
            a[0] = Qs[ar];
            a[1] = Qs[ar + 8 * QP_];
            a[2] = Qs[ar + 4];
            a[3] = Qs[ar + 8 * QP_ + 4];
            #pragma unroll
            for (int ni = 0; ni < 8; ni++) {
                uint32_t b[2];
                int br = (ni * 8 + r4) * QP_ + kb + c4;
                b[0] = Ks[br];
                b[1] = Ks[br + 4];
                mma_tf32(sf[ni], a, b);
            }
        }

        if (more) loadV(j0 + 64);   // overlap with softmax

        // online softmax (rows r4 and r4+8)
        float mxA = -1e30f, mxB = -1e30f;
        #pragma unroll
        for (int ni = 0; ni < 8; ni++) {
            mxA = fmaxf(mxA, fmaxf(sf[ni][0], sf[ni][1]));
            mxB = fmaxf(mxB, fmaxf(sf[ni][2], sf[ni][3]));
        }
        mxA = fmaxf(mxA, __shfl_xor_sync(0xffffffffu, mxA, 1));
        mxA = fmaxf(mxA, __shfl_xor_sync(0xffffffffu, mxA, 2));
        mxB = fmaxf(mxB, __shfl_xor_sync(0xffffffffu, mxB, 1));
        mxB = fmaxf(mxB, __shfl_xor_sync(0xffffffffu, mxB, 2));
        float mnA = fmaxf(mA, mxA), mnB = fmaxf(mB, mxB);
        float scA = __expf(mA - mnA), scB = __expf(mB - mnB);
        float sA = 0.f, sB = 0.f;
        int prA = (m0w + r4) * VP_;
        int prB = prA + 8 * VP_;
        #pragma unroll
        for (int ni = 0; ni < 8; ni++) {
            float e0 = __expf(sf[ni][0] - mnA);
            float e1 = __expf(sf[ni][1] - mnA);
            float e2 = __expf(sf[ni][2] - mnB);
            float e3 = __expf(sf[ni][3] - mnB);
            sA += e0 + e1; sB += e2 + e3;
            int cc = ni * 8 + c4 * 2;
            Ps[prA + cc] = f2tf32(e0); Ps[prA + cc + 1] = f2tf32(e1);
            Ps[prB + cc] = f2tf32(e2); Ps[prB + cc + 1] = f2tf32(e3);
        }
        sA += __shfl_xor_sync(0xffffffffu, sA, 1);
        sA += __shfl_xor_sync(0xffffffffu, sA, 2);
        sB += __shfl_xor_sync(0xffffffffu, sB, 1);
        sB += __shfl_xor_sync(0xffffffffu, sB, 2);
        lA = lA * scA + sA; lB = lB * scB + sB;
        mA = mnA; mB = mnB;
        #pragma unroll
        for (int ni = 0; ni < 16; ni++) {
            o[ni][0] *= scA; o[ni][1] *= scA;
            o[ni][2] *= scB; o[ni][3] *= scB;
        }
        __syncwarp();   // Ps rows warp-private

        // O += P V
        #pragma unroll
        for (int ks = 0; ks < 8; ks++) {
            int kb = ks * 8;
            uint32_t a[4];
            int ar = (m0w + r4) * VP_ + kb + c4;
            a[0] = Ps[ar];
            a[1] = Ps[ar + 8 * VP_];
            a[2] = Ps[ar + 4];
            a[3] = Ps[ar + 8 * VP_ + 4];
            #pragma unroll
            for (int ni = 0; ni < 16; ni++) {
                uint32_t b[2];
                int br = (ni * 8 + r4) * VP_ + kb + c4;
                b[0] = Vt[br];
                b[1] = Vt[br + 4];
                mma_tf32(o[ni], a, b);
            }
        }
    }

    float invA = 1.f / lA, invB = 1.f / lB;
    int rA = q0 + m0w + r4;
    float* OgA = g_res + (size_t)bh * S_ * DH_ + (size_t)rA * DH_;
    float* OgB = OgA + 8 * DH_;
    #pragma unroll
    for (int ni = 0; ni < 16; ni++) {
        int cc = ni * 8 + c4 * 2;
        float2 oa, ob;
        oa.x = o[ni][0] * invA; oa.y = o[ni][1] * invA;
        ob.x = o[ni][2] * invB; ob.y = o[ni][3] * invB;
        *(float2*)(OgA + cc) = oa;
        *(float2*)(OgB + cc) = ob;
    }
}

// ---------------------------------------------------------------------------
extern "C" void kernel_launch(void* const* d_in, const int* in_sizes, int n_in,
                              void* d_out, int out_size) {
    const float* q_src = (const float*)d_in[0];
    const float* k_src = (const float*)d_in[1];
    const float* v_src = (const float*)d_in[2];
    const float* Wq    = (const float*)d_in[3];
    const float* Wk    = (const float*)d_in[4];
    const float* Wv    = (const float*)d_in[5];
    const float* Wo    = (const float*)d_in[6];
    const float* sel_v = (const float*)d_in[7];
    const float* sel_o = (const float*)d_in[8];
    float* outp = (float*)d_out;

    cudaFuncSetAttribute(attn_tc_kernel, cudaFuncAttributeMaxDynamicSharedMemorySize, ATTN_SMEM);
    cudaFuncSetAttribute(gemm_tf32<1>, cudaFuncAttributeMaxDynamicSharedMemorySize, GSMEM_BYTES);
    cudaFuncSetAttribute(gemm_tf32<2>, cudaFuncAttributeMaxDynamicSharedMemorySize, GSMEM_BYTES);
    cudaFuncSetAttribute(gemm_tf32<3>, cudaFuncAttributeMaxDynamicSharedMemorySize, GSMEM_BYTES);

    float *gq, *gk, *gv, *gwvT, *gwoT, *gres;
    cudaGetSymbolAddress((void**)&gq, g_q);
    cudaGetSymbolAddress((void**)&gk, g_k);
    cudaGetSymbolAddress((void**)&gv, g_v);
    cudaGetSymbolAddress((void**)&gwvT, g_wvT);
    cudaGetSymbolAddress((void**)&gwoT, g_woT);
    cudaGetSymbolAddress((void**)&gres, g_res);

    const float scale = 0.29730177875068026f;  // 128^-0.25

    router_kernel<<<TOK_, 256>>>(q_src, k_src, sel_v, sel_o);

    // Wv [H,E,D,DH] -> WvT [(h,e,dh), d]
    transpose_kernel<<<dim3(DH_ / 32, D_ / 32, GE_), dim3(32, 8)>>>(Wv, gwvT, D_, DH_);
    // Wo flat [(h,e,dh), o] -> WoT [o, (h,e,dh)]
    transpose_kernel<<<dim3(D_ / 32, KEXP_ / 32, 1), dim3(32, 8)>>>(Wo, gwoT, KEXP_, D_);

    // merged q/k projections: M=4096, N=1024, K=1024; z=0 -> q, z=1 -> k
    gemm_tf32<1><<<dim3(D_ / 128, TOK_ / 128, 2), 256, GSMEM_BYTES>>>(
        q_src, Wq, gq, D_, 0, scale, k_src, Wk, gk);

    // per-head gated V: M=4096, N=128, K=E*D=4096, z=h
    gemm_tf32<3><<<dim3(1, TOK_ / 128, H_), 256, GSMEM_BYTES>>>(
        v_src, gwvT, gv, E_ * D_, 0, 1.0f, nullptr, nullptr, nullptr);

    attn_tc_kernel<<<dim3(S_ / 128, B_ * H_), 256, ATTN_SMEM>>>();

    // out: M=4096, N=1024, K=4096, A = gated g_res expansion (MODE 2)
    gemm_tf32<2><<<dim3(D_ / 128, TOK_ / 128), 256, GSMEM_BYTES>>>(
        gres, gwoT, outp, KEXP_, D_, 1.0f, nullptr, nullptr, nullptr);
}